// round 8
// baseline (speedup 1.0000x reference)
#include <cuda_runtime.h>
#include <cstdint>

// RRSVM rank-weighted pooling, 3x3 window, stride 2, pad 1.
// x: [32, 64, 112, 112] f32   s: [64, 3, 3] f32
// d_out (f32, concatenated): out [32,64,56,56], order [32,64,56,56,9]

#define BB 32
#define CC 64
#define HH 112
#define WW 112
#define HO 56
#define WO 56
#define PIX_PER_CH (HO * WO)      // 3136
#define NQ (BB * CC)              // 2048
#define TPB 256

__device__ __forceinline__ void stcs_f4(float4* p, float4 v) {
    asm volatile("st.global.cs.v4.f32 [%0], {%1,%2,%3,%4};"
                 :: "l"(p), "f"(v.x), "f"(v.y), "f"(v.z), "f"(v.w) : "memory");
}
__device__ __forceinline__ void stcs_f(float* p, float v) {
    asm volatile("st.global.cs.f32 [%0], %1;" :: "l"(p), "f"(v) : "memory");
}

__global__ void __launch_bounds__(TPB, 8) rrsvm_kernel(
        const float* __restrict__ x,
        const float* __restrict__ s,
        float* __restrict__ out,
        float* __restrict__ order,
        int write_order) {
    __shared__ __align__(16) float ord_sh[TPB * 9];  // order staging (16B for float4)
    __shared__ float s_sh[18];          // s rows for the (<=2) channels this block touches

    const int tid = threadIdx.x;
    const unsigned p0 = blockIdx.x * TPB;
    const unsigned p = p0 + tid;

    const int q_first = (int)(p0 / PIX_PER_CH);
    const int q = (int)(p / PIX_PER_CH);

    // Load the 1-2 needed s rows (9 floats each) into shared.
    if (tid < 18) {
        int qq = q_first + tid / 9;
        if (qq < NQ) s_sh[tid] = s[(qq & (CC - 1)) * 9 + (tid % 9)];
    }
    __syncthreads();

    const int cbase = (q - q_first) * 9;   // 0 or 9
    const int pix = (int)(p % PIX_PER_CH);
    const int wo = pix % WO;
    const int ho = pix / WO;
    const int lane = tid & 31;

    const float* xp = x + (unsigned)q * (HH * WW);
    const float* row0 = xp + (2 * ho - 1) * WW + 2 * wo;
    const bool h0v = (ho > 0);

    // Batch all main loads first (MLP=3), consumers afterwards.
    float2 bc0 = make_float2(0.0f, 0.0f), bc1, bc2;
    if (h0v) bc0 = *(const float2*)(row0);
    bc1 = *(const float2*)(row0 + WW);
    bc2 = *(const float2*)(row0 + 2 * WW);

    // Left column (col 2wo-1) = lane-1's bc.y; warps never straddle a
    // channel (3136 % 32 == 0). Lane 0 fixup loads, wo==0 -> padding 0.
    float l0 = __shfl_up_sync(0xffffffffu, bc0.y, 1);
    float l1 = __shfl_up_sync(0xffffffffu, bc1.y, 1);
    float l2 = __shfl_up_sync(0xffffffffu, bc2.y, 1);
    if (lane == 0 && wo > 0) {
        if (h0v) l0 = __ldg(row0 - 1);
        l1 = __ldg(row0 + WW - 1);
        l2 = __ldg(row0 + 2 * WW - 1);
    }
    if (wo == 0) { l0 = 0.0f; l1 = 0.0f; l2 = 0.0f; }
    if (!h0v) l0 = 0.0f;

    float v[9];
    v[0] = l0; v[1] = bc0.x; v[2] = bc0.y;
    v[3] = l1; v[4] = bc1.x; v[5] = bc1.y;
    v[6] = l2; v[7] = bc2.x; v[8] = bc2.y;

    // Pairwise ranks scaled by 4 (byte offsets), accumulated with FFMA-imm.
    // m = (v[j] > v[i]) ? 1.0f : 0.0f; strict-greater => ties keep index
    // order (stable argsort of -v). Exact small ints in f32.
    float rf[9];
    #pragma unroll
    for (int k = 0; k < 9; k++) rf[k] = (float)(4 * k);
    #pragma unroll
    for (int i = 0; i < 8; i++) {
        #pragma unroll
        for (int j = i + 1; j < 9; j++) {
            float m;
            asm("set.gt.f32.f32 %0, %1, %2;"
                : "=f"(m) : "f"(v[j]), "f"(v[i]));
            rf[i] = fmaf(m,  4.0f, rf[i]);
            rf[j] = fmaf(m, -4.0f, rf[j]);
        }
    }
    int ir[9];   // 4 * rank_k (byte offset)
    #pragma unroll
    for (int k = 0; k < 9; k++) ir[k] = (int)rf[k];

    // Weighted sum: out = sum_k v[k] * s[rank_k]
    const char* sp = (const char*)(s_sh + cbase);
    float sum = 0.0f;
    #pragma unroll
    for (int k = 0; k < 9; k++) {
        sum += v[k] * *(const float*)(sp + ir[k]);
    }
    stcs_f(out + p, sum);

    if (write_order) {
        // Scatter order indices: segment[rank_k] = k  (as float).
        char* my = (char*)(ord_sh + tid * 9);
        #pragma unroll
        for (int k = 0; k < 9; k++) {
            *(float*)(my + ir[k]) = (float)k;
        }
        __syncwarp();
        // Warp-coalesced vectorized streaming copy-out: 72 float4 per warp.
        const int w = tid >> 5;
        const float4* src = (const float4*)(ord_sh + w * 288);
        float4* dst = (float4*)(order + (p0 + (unsigned)w * 32) * 9);
        stcs_f4(dst + lane,      src[lane]);
        stcs_f4(dst + lane + 32, src[lane + 32]);
        if (lane < 8) stcs_f4(dst + lane + 64, src[lane + 64]);
    }
}

extern "C" void kernel_launch(void* const* d_in, const int* in_sizes, int n_in,
                              void* d_out, int out_size) {
    const float* x = (const float*)d_in[0];
    const float* s = (const float*)d_in[1];
    const long long NPIX = (long long)BB * CC * HO * WO;  // 6,422,528

    float* out = (float*)d_out;
    float* order = out + NPIX;
    int write_order = ((long long)out_size >= NPIX * 10LL) ? 1 : 0;

    const long long blocks = (NPIX + TPB - 1) / TPB;  // 25088, exact
    rrsvm_kernel<<<(unsigned)blocks, TPB>>>(x, s, out, order, write_order);
}

// round 9
// speedup vs baseline: 1.1126x; 1.1126x over previous
#include <cuda_runtime.h>
#include <cstdint>

// RRSVM rank-weighted pooling, 3x3 window, stride 2, pad 1.
// x: [32, 64, 112, 112] f32   s: [64, 3, 3] f32
// d_out (f32, concatenated): out [32,64,56,56], order [32,64,56,56,9]
// 2 horizontally-adjacent output pixels per thread.

#define BB 32
#define CC 64
#define HH 112
#define WW 112
#define HO 56
#define WO 56
#define PIX_PER_CH (HO * WO)      // 3136
#define PAIRS_PER_CH (PIX_PER_CH / 2)  // 1568
#define UPR (WO / 2)              // 28 thread-pairs per output row
#define NQ (BB * CC)              // 2048
#define TPB 256

__device__ __forceinline__ void stcs_f4(float4* p, float4 v) {
    asm volatile("st.global.cs.v4.f32 [%0], {%1,%2,%3,%4};"
                 :: "l"(p), "f"(v.x), "f"(v.y), "f"(v.z), "f"(v.w) : "memory");
}

// Compute ranks (x4, byte offsets) of 9 values; strict-greater => stable.
__device__ __forceinline__ void ranks9(const float v[9], int ir[9]) {
    float rf[9];
    #pragma unroll
    for (int k = 0; k < 9; k++) rf[k] = (float)(4 * k);
    #pragma unroll
    for (int i = 0; i < 8; i++) {
        #pragma unroll
        for (int j = i + 1; j < 9; j++) {
            float m;
            asm("set.gt.f32.f32 %0, %1, %2;"
                : "=f"(m) : "f"(v[j]), "f"(v[i]));
            rf[i] = fmaf(m,  4.0f, rf[i]);
            rf[j] = fmaf(m, -4.0f, rf[j]);
        }
    }
    #pragma unroll
    for (int k = 0; k < 9; k++) ir[k] = (int)rf[k];
}

__global__ void __launch_bounds__(TPB, 6) rrsvm_kernel(
        const float* __restrict__ x,
        const float* __restrict__ s,
        float* __restrict__ out,
        float* __restrict__ order,
        int write_order) {
    __shared__ __align__(16) float ord_sh[TPB * 18];  // 2 pixel-segments/thread
    __shared__ float s_sh[18];

    const int tid = threadIdx.x;
    const unsigned t0 = blockIdx.x * TPB;      // first pair index of block
    const unsigned t = t0 + tid;               // this thread's pair index

    const int q_first = (int)(t0 / PAIRS_PER_CH);
    const int q = (int)(t / PAIRS_PER_CH);

    if (tid < 18) {
        int qq = q_first + tid / 9;
        if (qq < NQ) s_sh[tid] = s[(qq & (CC - 1)) * 9 + (tid % 9)];
    }
    __syncthreads();

    const int cbase = (q - q_first) * 9;       // 0 or 9
    const int pr = (int)(t % PAIRS_PER_CH);
    const int ho = pr / UPR;
    const int u  = pr % UPR;                   // pixel A: wo=2u, pixel B: wo=2u+1
    const int lane = tid & 31;

    const float* xp = x + (unsigned)q * (HH * WW);
    const float* row0 = xp + (2 * ho - 1) * WW + 4 * u;
    const bool h0v = (ho > 0);

    // One float4 per window row covers cols 4u..4u+3 (16B-aligned).
    float4 r0 = make_float4(0.f, 0.f, 0.f, 0.f), r1, r2;
    if (h0v) r0 = *(const float4*)(row0);
    r1 = *(const float4*)(row0 + WW);
    r2 = *(const float4*)(row0 + 2 * WW);

    // Left col 4u-1 = lane-1's .w (consecutive t => u-1 same row when u>0).
    float l0 = __shfl_up_sync(0xffffffffu, r0.w, 1);
    float l1 = __shfl_up_sync(0xffffffffu, r1.w, 1);
    float l2 = __shfl_up_sync(0xffffffffu, r2.w, 1);
    if (lane == 0 && u > 0) {
        if (h0v) l0 = __ldg(row0 - 1);
        l1 = __ldg(row0 + WW - 1);
        l2 = __ldg(row0 + 2 * WW - 1);
    }
    if (u == 0) { l0 = 0.f; l1 = 0.f; l2 = 0.f; }   // wo==0 -> pad
    // (h0v==false already zeroed r0; l0 zeroed via r0.w path only if u==0,
    //  so force it:)
    if (!h0v) l0 = 0.f;

    const char* sp = (const char*)(s_sh + cbase);
    float2 res;

    // ---- pixel A: window cols 4u-1, 4u, 4u+1 ----
    {
        float v[9] = { l0, r0.x, r0.y,  l1, r1.x, r1.y,  l2, r2.x, r2.y };
        int ir[9];
        ranks9(v, ir);
        float sum = 0.f;
        #pragma unroll
        for (int k = 0; k < 9; k++) sum += v[k] * *(const float*)(sp + ir[k]);
        res.x = sum;
        if (write_order) {
            char* my = (char*)(ord_sh + tid * 18);
            #pragma unroll
            for (int k = 0; k < 9; k++) *(float*)(my + ir[k]) = (float)k;
        }
    }
    // ---- pixel B: window cols 4u+1, 4u+2, 4u+3 ----
    {
        float v[9] = { r0.y, r0.z, r0.w,  r1.y, r1.z, r1.w,  r2.y, r2.z, r2.w };
        int ir[9];
        ranks9(v, ir);
        float sum = 0.f;
        #pragma unroll
        for (int k = 0; k < 9; k++) sum += v[k] * *(const float*)(sp + ir[k]);
        res.y = sum;
        if (write_order) {
            char* my = (char*)(ord_sh + tid * 18 + 9);
            #pragma unroll
            for (int k = 0; k < 9; k++) *(float*)(my + ir[k]) = (float)k;
        }
    }

    *(float2*)(out + 2ull * t) = res;

    if (write_order) {
        __syncwarp();
        // Per-warp: 64 pixels * 9 = 576 contiguous floats = 144 float4.
        const int w = tid >> 5;
        const float4* src = (const float4*)(ord_sh + w * 576);
        float4* dst = (float4*)(order + ((unsigned long long)(t0 + w * 32)) * 18ull);
        #pragma unroll
        for (int k = 0; k < 4; k++) stcs_f4(dst + lane + 32 * k, src[lane + 32 * k]);
        if (lane < 16) stcs_f4(dst + lane + 128, src[lane + 128]);
    }
}

extern "C" void kernel_launch(void* const* d_in, const int* in_sizes, int n_in,
                              void* d_out, int out_size) {
    const float* x = (const float*)d_in[0];
    const float* s = (const float*)d_in[1];
    const long long NPIX = (long long)BB * CC * HO * WO;  // 6,422,528

    float* out = (float*)d_out;
    float* order = out + NPIX;
    int write_order = ((long long)out_size >= NPIX * 10LL) ? 1 : 0;

    const long long pairs = NPIX / 2;                    // 3,211,264
    const long long blocks = (pairs + TPB - 1) / TPB;    // 12544, exact
    rrsvm_kernel<<<(unsigned)blocks, TPB>>>(x, s, out, order, write_order);
}